// round 2
// baseline (speedup 1.0000x reference)
#include <cuda_runtime.h>
#include <math.h>

// Problem constants
#define BB 16
#define CC 512
#define HH 32
#define WW 32
#define HW (HH*WW)          // 1024
#define P  (BB*HW)          // 16384 positions
#define NN 16384            // codebook size
#define DD 32               // embedding dim
#define NSPLIT 8
#define NSLICE (NN/NSPLIT)  // 2048
#define TILE 128            // codes per smem tile
#define OUT_ELEMS (BB*CC*HW) // 8388608

typedef unsigned long long u64;

// Scratch (allocation-free rule: __device__ globals)
__device__ float g_e[NN*DD];            // normalized codebook
__device__ float g_z[P*DD];             // normalized projected queries, [p][d]
__device__ float g_psim[P*NSPLIT];      // partial best sims
__device__ int   g_pidx[P*NSPLIT];      // partial best indices
__device__ int   g_idx[P];              // final argmax per position
__device__ float g_s[P];                // final best sim per position
__device__ int   g_hist[NN];            // usage histogram

// ---------------------------------------------------------------- f32x2 helpers
__device__ __forceinline__ u64 fma2(u64 a, u64 b, u64 c) {
    u64 d;
    asm("fma.rn.f32x2 %0, %1, %2, %3;" : "=l"(d) : "l"(a), "l"(b), "l"(c));
    return d;
}
__device__ __forceinline__ u64 add2(u64 a, u64 b) {
    u64 d;
    asm("add.rn.f32x2 %0, %1, %2;" : "=l"(d) : "l"(a), "l"(b));
    return d;
}
__device__ __forceinline__ float hsum2(u64 a) {
    unsigned lo, hi;
    asm("mov.b64 {%0, %1}, %2;" : "=r"(lo), "=r"(hi) : "l"(a));
    return __uint_as_float(lo) + __uint_as_float(hi);
}

// ---------------------------------------------------------------- init
__global__ void k_init() {
    int i = blockIdx.x * blockDim.x + threadIdx.x;
    if (i < NN) g_hist[i] = 0;
}

// ---------------------------------------------------------------- normalize codebook
__global__ void k_norm_emb(const float* __restrict__ emb) {
    int r = blockIdx.x * blockDim.x + threadIdx.x;  // row 0..NN-1
    if (r >= NN) return;
    const float4* src = (const float4*)(emb + r * DD);
    float4 v[8];
    float sum = 0.f;
#pragma unroll
    for (int q = 0; q < 8; q++) {
        v[q] = src[q];
        sum += v[q].x*v[q].x + v[q].y*v[q].y + v[q].z*v[q].z + v[q].w*v[q].w;
    }
    float inv = 1.f / fmaxf(sqrtf(sum), 1e-6f);
    float4* dst = (float4*)(g_e + r * DD);
#pragma unroll
    for (int q = 0; q < 8; q++) {
        float4 o = v[q];
        o.x *= inv; o.y *= inv; o.z *= inv; o.w *= inv;
        dst[q] = o;
    }
}

// ---------------------------------------------------------------- project + normalize z
// block = 128 threads = 128 consecutive positions (same batch b)
__global__ void k_project(const float* __restrict__ enc,
                          const float* __restrict__ proj_w,   // [D][C]
                          const float* __restrict__ proj_b) { // [D]
    __shared__ float ws[256 * DD];   // chunk of proj_w transposed: ws[cc][d], 32KB
    int tid = threadIdx.x;
    int p = blockIdx.x * 128 + tid;
    int b = p >> 10;
    int hw = p & 1023;
    const float* encp = enc + (b * CC) * HW + hw;

    float4 acc[8];
#pragma unroll
    for (int q = 0; q < 8; q++) acc[q] = make_float4(0.f, 0.f, 0.f, 0.f);

    for (int chunk = 0; chunk < 2; chunk++) {
        int c0 = chunk * 256;
        __syncthreads();
        // load ws[cc*32+d] = proj_w[d*512 + c0+cc]
        for (int i = tid; i < 256 * DD; i += 128) {
            int ccl = i >> 5, d = i & 31;
            ws[i] = proj_w[d * CC + c0 + ccl];
        }
        __syncthreads();
        for (int ccl = 0; ccl < 256; ccl++) {
            float ev = encp[(c0 + ccl) * HW];
            const float4* wp = (const float4*)(ws + ccl * DD);
#pragma unroll
            for (int q = 0; q < 8; q++) {
                float4 w4 = wp[q];
                acc[q].x += ev * w4.x;
                acc[q].y += ev * w4.y;
                acc[q].z += ev * w4.z;
                acc[q].w += ev * w4.w;
            }
        }
    }
    // add bias, normalize over D
    float sum = 0.f;
#pragma unroll
    for (int q = 0; q < 8; q++) {
        acc[q].x += proj_b[q*4+0];
        acc[q].y += proj_b[q*4+1];
        acc[q].z += proj_b[q*4+2];
        acc[q].w += proj_b[q*4+3];
        sum += acc[q].x*acc[q].x + acc[q].y*acc[q].y + acc[q].z*acc[q].z + acc[q].w*acc[q].w;
    }
    float inv = 1.f / fmaxf(sqrtf(sum), 1e-6f);
    float4* dst = (float4*)(g_z + p * DD);
#pragma unroll
    for (int q = 0; q < 8; q++) {
        float4 o = acc[q];
        o.x *= inv; o.y *= inv; o.z *= inv; o.w *= inv;
        dst[q] = o;
    }
}

// ---------------------------------------------------------------- argmax search
// grid (P/128, NSPLIT); each thread: one position, scans NSLICE codes via smem tiles.
// Inner dot product uses packed fma.rn.f32x2 (FFMA2): 16 packed FMAs + 3 packed
// adds + 1 scalar add per code, vs 35 scalar fma-pipe ops in the naive version.
__global__ void k_search() {
    __shared__ float sc[TILE * DD];   // 16KB
    int tid = threadIdx.x;
    int p = blockIdx.x * 128 + tid;
    int n0base = blockIdx.y * NSLICE;

    // z as 8x ulonglong2 = 16 packed f32x2 values
    ulonglong2 z2[8];
    const ulonglong2* zp = (const ulonglong2*)(g_z + p * DD);
#pragma unroll
    for (int q = 0; q < 8; q++) z2[q] = zp[q];

    float best = -1e30f;
    int bidx = n0base;

    for (int t = 0; t < NSLICE / TILE; t++) {
        int n0 = n0base + t * TILE;
        __syncthreads();
        {
            const float4* gsrc = (const float4*)(g_e + n0 * DD);
            float4* sdst = (float4*)sc;
            for (int i = tid; i < TILE * DD / 4; i += 128) sdst[i] = gsrc[i];
        }
        __syncthreads();
#pragma unroll 2
        for (int j = 0; j < TILE; j++) {
            const ulonglong2* cp = (const ulonglong2*)(sc + j * DD);
            u64 a0 = 0ull, a1 = 0ull, a2 = 0ull, a3 = 0ull;
#pragma unroll
            for (int q = 0; q < 8; q += 2) {
                ulonglong2 c0 = cp[q];
                ulonglong2 c1 = cp[q + 1];
                a0 = fma2(c0.x, z2[q].x, a0);
                a1 = fma2(c0.y, z2[q].y, a1);
                a2 = fma2(c1.x, z2[q + 1].x, a2);
                a3 = fma2(c1.y, z2[q + 1].y, a3);
            }
            a0 = add2(a0, a1);
            a2 = add2(a2, a3);
            a0 = add2(a0, a2);
            float s = hsum2(a0);
            if (s > best) { best = s; bidx = n0 + j; }
        }
    }
    g_psim[p * NSPLIT + blockIdx.y] = best;
    g_pidx[p * NSPLIT + blockIdx.y] = bidx;
}

// ---------------------------------------------------------------- finalize per position
__global__ void k_finalize() {
    int p = blockIdx.x * blockDim.x + threadIdx.x;
    if (p >= P) return;
    float best = -1e30f;
    int bi = 0;
#pragma unroll
    for (int s = 0; s < NSPLIT; s++) {
        float v = g_psim[p * NSPLIT + s];
        int id = g_pidx[p * NSPLIT + s];
        if (v > best) { best = v; bi = id; }
    }
    g_idx[p] = bi;
    g_s[p] = best;
    atomicAdd(&g_hist[bi], 1);   // integer atomic: deterministic
}

// ---------------------------------------------------------------- output GEMM
// block = 128 threads = 128 consecutive positions; exp_w chunked in smem
__global__ void k_output(const float* __restrict__ exp_w,   // [C][D]
                         const float* __restrict__ exp_b,   // [C]
                         float* __restrict__ out) {
    __shared__ float ws[128 * DD];   // 16KB, chunk of exp_w
    __shared__ float wb[128];
    int tid = threadIdx.x;
    int p = blockIdx.x * 128 + tid;
    int b = p >> 10;
    int hw = p & 1023;

    ulonglong2 cz[8];
    {
        int idx = g_idx[p];
        const ulonglong2* cp = (const ulonglong2*)(g_e + idx * DD);
#pragma unroll
        for (int q = 0; q < 8; q++) cz[q] = cp[q];
    }
    float* outp = out + (b * CC) * HW + hw;

    for (int chunk = 0; chunk < 4; chunk++) {
        int c0 = chunk * 128;
        __syncthreads();
        for (int i = tid; i < 128 * DD; i += 128) ws[i] = exp_w[c0 * DD + i]; // contiguous
        wb[tid] = exp_b[c0 + tid];
        __syncthreads();
        for (int ccl = 0; ccl < 128; ccl++) {
            const ulonglong2* wp = (const ulonglong2*)(ws + ccl * DD);
            u64 a0 = 0ull, a1 = 0ull, a2 = 0ull, a3 = 0ull;
#pragma unroll
            for (int q = 0; q < 8; q += 2) {
                ulonglong2 w0 = wp[q];
                ulonglong2 w1 = wp[q + 1];
                a0 = fma2(w0.x, cz[q].x, a0);
                a1 = fma2(w0.y, cz[q].y, a1);
                a2 = fma2(w1.x, cz[q + 1].x, a2);
                a3 = fma2(w1.y, cz[q + 1].y, a3);
            }
            a0 = add2(a0, a1);
            a2 = add2(a2, a3);
            a0 = add2(a0, a2);
            outp[(c0 + ccl) * HW] = hsum2(a0) + wb[ccl];
        }
    }
}

// ---------------------------------------------------------------- scalars (loss, perplexity)
// single block, deterministic strided partials + tree reduce
__global__ void k_scalars(float* __restrict__ out) {
    __shared__ float red[256];
    int tid = threadIdx.x;

    // sum of best sims -> loss = mean((z - e)^2) = (2P - 2*sum)/(P*D)
    float ls = 0.f;
    for (int i = tid; i < P; i += 256) ls += g_s[i];
    red[tid] = ls;
    __syncthreads();
    for (int off = 128; off > 0; off >>= 1) {
        if (tid < off) red[tid] += red[tid + off];
        __syncthreads();
    }
    float sum_s = red[0];
    __syncthreads();

    // entropy of usage histogram -> perplexity
    float hs = 0.f;
    const float invP = 1.0f / (float)P;
    for (int i = tid; i < NN; i += 256) {
        float u = (float)g_hist[i] * invP;
        hs += -u * logf(u + 1e-6f);
    }
    red[tid] = hs;
    __syncthreads();
    for (int off = 128; off > 0; off >>= 1) {
        if (tid < off) red[tid] += red[tid + off];
        __syncthreads();
    }
    if (tid == 0) {
        out[OUT_ELEMS]     = (2.f * (float)P - 2.f * sum_s) / ((float)P * (float)DD);
        out[OUT_ELEMS + 1] = expf(red[0]);
    }
}

// ---------------------------------------------------------------- launch
extern "C" void kernel_launch(void* const* d_in, const int* in_sizes, int n_in,
                              void* d_out, int out_size) {
    const float* encodings = (const float*)d_in[0];
    const float* emb_weight = (const float*)d_in[1];
    const float* proj_w = (const float*)d_in[2];
    const float* proj_b = (const float*)d_in[3];
    const float* exp_w = (const float*)d_in[4];
    const float* exp_b = (const float*)d_in[5];
    float* out = (float*)d_out;

    k_init<<<NN / 256, 256>>>();
    k_norm_emb<<<NN / 128, 128>>>(emb_weight);
    k_project<<<P / 128, 128>>>(encodings, proj_w, proj_b);
    k_search<<<dim3(P / 128, NSPLIT), 128>>>();
    k_finalize<<<P / 256, 256>>>();
    k_output<<<P / 128, 128>>>(exp_w, exp_b, out);
    k_scalars<<<1, 256>>>(out);
}

// round 4
// speedup vs baseline: 1.2140x; 1.2140x over previous
#include <cuda_runtime.h>
#include <math.h>

// Problem constants
#define BB 16
#define CC 512
#define HH 32
#define WW 32
#define HW (HH*WW)          // 1024
#define P  (BB*HW)          // 16384 positions
#define NN 16384            // codebook size
#define DD 32               // embedding dim
#define NSPLIT 32
#define NSLICE (NN/NSPLIT)  // 512
#define TILE 128            // codes per smem tile
#define POSB 4              // positions per thread in search
#define OUT_ELEMS (BB*CC*HW) // 8388608

typedef unsigned long long u64;

// Scratch (allocation-free rule: __device__ globals)
__device__ float g_e[NN*DD];            // normalized codebook
__device__ float g_z[P*DD];             // normalized projected queries, [p][d]
__device__ float g_psim[P*NSPLIT];      // partial best sims
__device__ int   g_pidx[P*NSPLIT];      // partial best indices
__device__ int   g_idx[P];              // final argmax per position
__device__ float g_s[P];                // final best sim per position
__device__ int   g_hist[NN];            // usage histogram

// ---------------------------------------------------------------- f32x2 helpers
__device__ __forceinline__ u64 fma2(u64 a, u64 b, u64 c) {
    u64 d;
    asm("fma.rn.f32x2 %0, %1, %2, %3;" : "=l"(d) : "l"(a), "l"(b), "l"(c));
    return d;
}
__device__ __forceinline__ u64 add2(u64 a, u64 b) {
    u64 d;
    asm("add.rn.f32x2 %0, %1, %2;" : "=l"(d) : "l"(a), "l"(b));
    return d;
}
__device__ __forceinline__ float hsum2(u64 a) {
    unsigned lo, hi;
    asm("mov.b64 {%0, %1}, %2;" : "=r"(lo), "=r"(hi) : "l"(a));
    return __uint_as_float(lo) + __uint_as_float(hi);
}

// ---------------------------------------------------------------- init
__global__ void k_init() {
    int i = blockIdx.x * blockDim.x + threadIdx.x;
    if (i < NN) g_hist[i] = 0;
}

// ---------------------------------------------------------------- normalize codebook
__global__ void k_norm_emb(const float* __restrict__ emb) {
    int r = blockIdx.x * blockDim.x + threadIdx.x;  // row 0..NN-1
    if (r >= NN) return;
    const float4* src = (const float4*)(emb + r * DD);
    float4 v[8];
    float sum = 0.f;
#pragma unroll
    for (int q = 0; q < 8; q++) {
        v[q] = src[q];
        sum += v[q].x*v[q].x + v[q].y*v[q].y + v[q].z*v[q].z + v[q].w*v[q].w;
    }
    float inv = 1.f / fmaxf(sqrtf(sum), 1e-6f);
    float4* dst = (float4*)(g_e + r * DD);
#pragma unroll
    for (int q = 0; q < 8; q++) {
        float4 o = v[q];
        o.x *= inv; o.y *= inv; o.z *= inv; o.w *= inv;
        dst[q] = o;
    }
}

// ---------------------------------------------------------------- project + normalize z
// block = 128 threads = 128 consecutive positions (same batch b)
__global__ void k_project(const float* __restrict__ enc,
                          const float* __restrict__ proj_w,   // [D][C]
                          const float* __restrict__ proj_b) { // [D]
    __shared__ float ws[256 * DD];   // chunk of proj_w transposed: ws[cc][d], 32KB
    int tid = threadIdx.x;
    int p = blockIdx.x * 128 + tid;
    int b = p >> 10;
    int hw = p & 1023;
    const float* encp = enc + (b * CC) * HW + hw;

    float4 acc[8];
#pragma unroll
    for (int q = 0; q < 8; q++) acc[q] = make_float4(0.f, 0.f, 0.f, 0.f);

    for (int chunk = 0; chunk < 2; chunk++) {
        int c0 = chunk * 256;
        __syncthreads();
        // load ws[cc*32+d] = proj_w[d*512 + c0+cc]
        for (int i = tid; i < 256 * DD; i += 128) {
            int ccl = i >> 5, d = i & 31;
            ws[i] = proj_w[d * CC + c0 + ccl];
        }
        __syncthreads();
        for (int ccl = 0; ccl < 256; ccl++) {
            float ev = encp[(c0 + ccl) * HW];
            const float4* wp = (const float4*)(ws + ccl * DD);
#pragma unroll
            for (int q = 0; q < 8; q++) {
                float4 w4 = wp[q];
                acc[q].x += ev * w4.x;
                acc[q].y += ev * w4.y;
                acc[q].z += ev * w4.z;
                acc[q].w += ev * w4.w;
            }
        }
    }
    // add bias, normalize over D
    float sum = 0.f;
#pragma unroll
    for (int q = 0; q < 8; q++) {
        acc[q].x += proj_b[q*4+0];
        acc[q].y += proj_b[q*4+1];
        acc[q].z += proj_b[q*4+2];
        acc[q].w += proj_b[q*4+3];
        sum += acc[q].x*acc[q].x + acc[q].y*acc[q].y + acc[q].z*acc[q].z + acc[q].w*acc[q].w;
    }
    float inv = 1.f / fmaxf(sqrtf(sum), 1e-6f);
    float4* dst = (float4*)(g_z + p * DD);
#pragma unroll
    for (int q = 0; q < 8; q++) {
        float4 o = acc[q];
        o.x *= inv; o.y *= inv; o.z *= inv; o.w *= inv;
        dst[q] = o;
    }
}

// ---------------------------------------------------------------- argmax search
// Register-tiled: each thread owns POSB=4 positions (z in registers); per code j
// the 32-float code vector is loaded from smem ONCE (8 LDS.128) and reused for
// all 4 positions -> LDS per (pos,code) = 2 instead of 8. fma pipe becomes the
// binding resource (16 FFMA2 + 1 ADD2 + 1 FADD per pos*code).
// grid (P/(128*POSB), NSPLIT) = (32, 32); block 128.
__global__ void __launch_bounds__(128) k_search() {
    __shared__ float sc[TILE * DD];   // 16KB
    int tid = threadIdx.x;
    int pbase = blockIdx.x * (128 * POSB) + tid;   // positions pbase + m*128
    int n0base = blockIdx.y * NSLICE;

    ulonglong2 z2[POSB][8];
#pragma unroll
    for (int m = 0; m < POSB; m++) {
        const ulonglong2* zp = (const ulonglong2*)(g_z + (pbase + m * 128) * DD);
#pragma unroll
        for (int q = 0; q < 8; q++) z2[m][q] = zp[q];
    }

    float best[POSB];
    int bidx[POSB];
#pragma unroll
    for (int m = 0; m < POSB; m++) { best[m] = -1e30f; bidx[m] = n0base; }

    for (int t = 0; t < NSLICE / TILE; t++) {     // 4 tiles
        int n0 = n0base + t * TILE;
        __syncthreads();
        {
            const float4* gsrc = (const float4*)(g_e + n0 * DD);
            float4* sdst = (float4*)sc;
            for (int i = tid; i < TILE * DD / 4; i += 128) sdst[i] = gsrc[i];
        }
        __syncthreads();
#pragma unroll 2
        for (int j = 0; j < TILE; j++) {
            const ulonglong2* cp = (const ulonglong2*)(sc + j * DD);
            ulonglong2 c[8];
#pragma unroll
            for (int q = 0; q < 8; q++) c[q] = cp[q];
#pragma unroll
            for (int m = 0; m < POSB; m++) {
                u64 a0 = 0ull, a1 = 0ull;
#pragma unroll
                for (int q = 0; q < 8; q++) {
                    a0 = fma2(c[q].x, z2[m][q].x, a0);
                    a1 = fma2(c[q].y, z2[m][q].y, a1);
                }
                a0 = add2(a0, a1);
                float s = hsum2(a0);
                if (s > best[m]) { best[m] = s; bidx[m] = n0 + j; }
            }
        }
    }
#pragma unroll
    for (int m = 0; m < POSB; m++) {
        g_psim[(pbase + m * 128) * NSPLIT + blockIdx.y] = best[m];
        g_pidx[(pbase + m * 128) * NSPLIT + blockIdx.y] = bidx[m];
    }
}

// ---------------------------------------------------------------- finalize per position
__global__ void k_finalize() {
    int p = blockIdx.x * blockDim.x + threadIdx.x;
    if (p >= P) return;
    float best = -1e30f;
    int bi = 0;
#pragma unroll 8
    for (int s = 0; s < NSPLIT; s++) {
        float v = g_psim[p * NSPLIT + s];
        int id = g_pidx[p * NSPLIT + s];
        if (v > best) { best = v; bi = id; }
    }
    g_idx[p] = bi;
    g_s[p] = best;
    atomicAdd(&g_hist[bi], 1);   // integer atomic: deterministic
}

// ---------------------------------------------------------------- output GEMM
// block = 128 threads = 128 consecutive positions; exp_w chunked in smem
__global__ void k_output(const float* __restrict__ exp_w,   // [C][D]
                         const float* __restrict__ exp_b,   // [C]
                         float* __restrict__ out) {
    __shared__ float ws[128 * DD];   // 16KB, chunk of exp_w
    __shared__ float wb[128];
    int tid = threadIdx.x;
    int p = blockIdx.x * 128 + tid;
    int b = p >> 10;
    int hw = p & 1023;

    ulonglong2 cz[8];
    {
        int idx = g_idx[p];
        const ulonglong2* cp = (const ulonglong2*)(g_e + idx * DD);
#pragma unroll
        for (int q = 0; q < 8; q++) cz[q] = cp[q];
    }
    float* outp = out + (b * CC) * HW + hw;

    for (int chunk = 0; chunk < 4; chunk++) {
        int c0 = chunk * 128;
        __syncthreads();
        for (int i = tid; i < 128 * DD; i += 128) ws[i] = exp_w[c0 * DD + i]; // contiguous
        wb[tid] = exp_b[c0 + tid];
        __syncthreads();
        for (int ccl = 0; ccl < 128; ccl++) {
            const ulonglong2* wp = (const ulonglong2*)(ws + ccl * DD);
            u64 a0 = 0ull, a1 = 0ull, a2 = 0ull, a3 = 0ull;
#pragma unroll
            for (int q = 0; q < 8; q += 2) {
                ulonglong2 w0 = wp[q];
                ulonglong2 w1 = wp[q + 1];
                a0 = fma2(w0.x, cz[q].x, a0);
                a1 = fma2(w0.y, cz[q].y, a1);
                a2 = fma2(w1.x, cz[q + 1].x, a2);
                a3 = fma2(w1.y, cz[q + 1].y, a3);
            }
            a0 = add2(a0, a1);
            a2 = add2(a2, a3);
            a0 = add2(a0, a2);
            outp[(c0 + ccl) * HW] = hsum2(a0) + wb[ccl];
        }
    }
}

// ---------------------------------------------------------------- scalars (loss, perplexity)
// single block, deterministic strided partials + tree reduce
__global__ void k_scalars(float* __restrict__ out) {
    __shared__ float red[256];
    int tid = threadIdx.x;

    // sum of best sims -> loss = mean((z - e)^2) = (2P - 2*sum)/(P*D)
    float ls = 0.f;
    for (int i = tid; i < P; i += 256) ls += g_s[i];
    red[tid] = ls;
    __syncthreads();
    for (int off = 128; off > 0; off >>= 1) {
        if (tid < off) red[tid] += red[tid + off];
        __syncthreads();
    }
    float sum_s = red[0];
    __syncthreads();

    // entropy of usage histogram -> perplexity
    float hs = 0.f;
    const float invP = 1.0f / (float)P;
    for (int i = tid; i < NN; i += 256) {
        float u = (float)g_hist[i] * invP;
        hs += -u * logf(u + 1e-6f);
    }
    red[tid] = hs;
    __syncthreads();
    for (int off = 128; off > 0; off >>= 1) {
        if (tid < off) red[tid] += red[tid + off];
        __syncthreads();
    }
    if (tid == 0) {
        out[OUT_ELEMS]     = (2.f * (float)P - 2.f * sum_s) / ((float)P * (float)DD);
        out[OUT_ELEMS + 1] = expf(red[0]);
    }
}

// ---------------------------------------------------------------- launch
extern "C" void kernel_launch(void* const* d_in, const int* in_sizes, int n_in,
                              void* d_out, int out_size) {
    const float* encodings = (const float*)d_in[0];
    const float* emb_weight = (const float*)d_in[1];
    const float* proj_w = (const float*)d_in[2];
    const float* proj_b = (const float*)d_in[3];
    const float* exp_w = (const float*)d_in[4];
    const float* exp_b = (const float*)d_in[5];
    float* out = (float*)d_out;

    k_init<<<NN / 256, 256>>>();
    k_norm_emb<<<NN / 128, 128>>>(emb_weight);
    k_project<<<P / 128, 128>>>(encodings, proj_w, proj_b);
    k_search<<<dim3(P / (128 * POSB), NSPLIT), 128>>>();
    k_finalize<<<P / 256, 256>>>();
    k_output<<<P / 128, 128>>>(exp_w, exp_b, out);
    k_scalars<<<1, 256>>>(out);
}